// round 2
// baseline (speedup 1.0000x reference)
#include <cuda_runtime.h>
#include <math.h>

#define NELEM 16384
#define SCORE_LIMIT 8192
#define NT 1024
#define EPT 16   // elements per thread (NELEM / NT)

__global__ __launch_bounds__(NT, 1)
void connect_attention_fused(const float* __restrict__ x,
                             const float* __restrict__ w7,
                             float* __restrict__ out)
{
    extern __shared__ unsigned char smem_raw[];
    float*        sx     = (float*)smem_raw;                 // NELEM + 8 floats (4 pad each side)
    float*        sxp    = sx + 4;                           // logical x base
    unsigned int* sb     = (unsigned int*)(sx + NELEM + 8);  // NELEM score bit patterns
    unsigned int* hist   = (unsigned int*)(sb + NELEM);      // 256 bins
    unsigned int* eqmask = hist + 256;                       // 512 words (NELEM/32)

    __shared__ unsigned int s_prefix, s_remk;
    __shared__ float sw[8];

    const int tid  = threadIdx.x;
    const int lane = tid & 31;

    if (tid < 7) sw[tid] = w7[tid];
    if (tid < 4) { sx[tid] = 0.0f; sxp[NELEM + tid] = 0.0f; }   // zero padding

    // ---- load x (coalesced, striped) ----
    #pragma unroll
    for (int r = 0; r < EPT; ++r)
        sxp[tid + r * NT] = x[tid + r * NT];
    __syncthreads();

    const float w0 = sw[0], w1 = sw[1], w2 = sw[2], w3 = sw[3],
                w4 = sw[4], w5 = sw[5], w6 = sw[6];

    // ---- conv 'same' (y[n] = sum_j x[n+j-3]*w[j]) + sigmoid ----
    #pragma unroll
    for (int r = 0; r < EPT; ++r) {
        int i = tid + r * NT;
        const float* p = sxp + i - 3;
        float y;
        y = p[0] * w0;
        y = fmaf(p[1], w1, y);
        y = fmaf(p[2], w2, y);
        y = fmaf(p[3], w3, y);
        y = fmaf(p[4], w4, y);
        y = fmaf(p[5], w5, y);
        y = fmaf(p[6], w6, y);
        float s = 1.0f / (1.0f + expf(-y));
        sb[i] = __float_as_uint(s);     // positive floats: bit order == value order
    }
    __syncthreads();

    // ---- 4-pass radix select: find rank-8192 threshold under stable ordering ----
    // Atomics are warp-aggregated via match_any: the score distribution is
    // heavily skewed (scores cluster in (0.3,0.7) so pass 0 hits ~2 bins),
    // which would otherwise serialize 16K same-address smem atomics.
    unsigned int prefix = 0;        // value of selected high bits so far
    unsigned int remk   = SCORE_LIMIT;

    for (int pass = 0; pass < 4; ++pass) {
        const int shift = 24 - 8 * pass;

        if (tid < 256) hist[tid] = 0;
        __syncthreads();

        #pragma unroll
        for (int r = 0; r < EPT; ++r) {
            unsigned int b = sb[tid + r * NT];
            bool cand = (pass == 0) || ((b >> (shift + 8)) == prefix);
            int bin = cand ? (int)((b >> shift) & 255u) : -1;
            unsigned int m = __match_any_sync(0xffffffffu, bin);
            int leader = __ffs(m) - 1;
            if (lane == leader && bin >= 0)
                atomicAdd(&hist[bin], (unsigned int)__popc(m));
        }
        __syncthreads();

        // warp 0: find the bin containing rank 'remk'
        if (tid < 32) {
            unsigned int lh[8];
            unsigned int lsum = 0;
            #pragma unroll
            for (int q = 0; q < 8; ++q) { lh[q] = hist[tid * 8 + q]; lsum += lh[q]; }
            // inclusive scan across lanes
            unsigned int inc = lsum;
            #pragma unroll
            for (int o = 1; o < 32; o <<= 1) {
                unsigned int v = __shfl_up_sync(0xffffffffu, inc, o);
                if (tid >= o) inc += v;
            }
            unsigned int excl = inc - lsum;
            if (excl < remk && remk <= inc) {   // exactly one lane
                unsigned int cum = excl;
                int bin = tid * 8;
                #pragma unroll
                for (int q = 0; q < 8; ++q) {
                    if (cum + lh[q] >= remk) { bin = tid * 8 + q; break; }
                    cum += lh[q];
                }
                s_prefix = (prefix << 8) | (unsigned int)bin;
                s_remk   = remk - cum;
            }
        }
        __syncthreads();
        prefix = s_prefix;
        remk   = s_remk;
        // next pass's hist-zero + sync separates this read from the next write
    }

    const unsigned int T = prefix;   // exact score bits at the boundary
    // remk = number of elements equal to T that are kept (smallest indices first)

    // ---- tie bitmask ----
    if (tid < 512) eqmask[tid] = 0;
    __syncthreads();
    #pragma unroll
    for (int r = 0; r < EPT; ++r) {
        int i = tid + r * NT;
        if (sb[i] == T) atomicOr(&eqmask[i >> 5], 1u << (i & 31));
    }
    __syncthreads();

    // ---- emit outputs ----
    #pragma unroll
    for (int r = 0; r < EPT; ++r) {
        int i = tid + r * NT;
        unsigned int b = sb[i];
        float s = __uint_as_float(b);
        bool keep;
        if (b < T)      keep = true;
        else if (b > T) keep = false;
        else {
            // stable tie-break: rank among equals by ascending index
            unsigned int rank = 0;
            int wrd = i >> 5;
            for (int q = 0; q < wrd; ++q) rank += __popc(eqmask[q]);
            rank += __popc(eqmask[wrd] & ((1u << (i & 31)) - 1u));
            keep = (rank < remk);
        }
        out[i]         = keep ? sxp[i] * (s + 1.0f) : 0.0f;
        out[NELEM + i] = s;
    }
}

extern "C" void kernel_launch(void* const* d_in, const int* in_sizes, int n_in,
                              void* d_out, int out_size)
{
    const float* x = (const float*)d_in[0];
    const float* w = (const float*)d_in[1];
    // defensive: metadata order should be (x[16384], conv_w[7])
    if (n_in >= 2 && in_sizes[0] == 7) {
        const float* t = x; x = w; w = t;
    }
    float* out = (float*)d_out;

    size_t smem = (size_t)(NELEM + 8) * 4 + (size_t)NELEM * 4 + 256 * 4 + 512 * 4;
    cudaFuncSetAttribute(connect_attention_fused,
                         cudaFuncAttributeMaxDynamicSharedMemorySize, (int)smem);
    connect_attention_fused<<<1, NT, smem>>>(x, w, out);
}

// round 3
// speedup vs baseline: 1.2790x; 1.2790x over previous
#include <cuda_runtime.h>
#include <math.h>

#define NELEM 16384
#define KSEL  8192
#define NT    512
#define EPT   32          // NELEM / NT
#define NWARP 16
#define POOLA 4096
#define POOLB 256
#define SENT  0xFFFFFFFFu

__global__ __launch_bounds__(NT, 1)
void connect_attention_fused(const float* __restrict__ x,
                             const float* __restrict__ w7,
                             float* __restrict__ out)
{
    extern __shared__ unsigned char smem_raw[];
    float*        sx    = (float*)smem_raw;                   // NELEM+8 floats (4 pad each side)
    float*        sxp   = sx + 4;
    unsigned int* poolA = (unsigned int*)(sx + NELEM + 8);    // POOLA
    unsigned int* poolB = poolA + POOLA;                      // POOLB
    unsigned int* eqm   = poolB + POOLB;                      // 512 words
    unsigned int* wred  = eqm + 512;                          // NWARP

    __shared__ float sw[8];
    __shared__ unsigned int s_lo, s_hi, s_cb, s_chi, s_baseA, s_baseB, s_T, s_cbF, s_pc;
    __shared__ unsigned int s_chunk[32];

    const int tid  = threadIdx.x;
    const int lane = tid & 31;
    const int wid  = tid >> 5;

    if (tid < 7) sw[tid] = w7[tid];
    if (tid < 4) { sx[tid] = 0.0f; sxp[NELEM + tid] = 0.0f; }

    // ---- stage x into smem (vectorized, coalesced) ----
    {
        const float4* x4  = (const float4*)x;
        float4*       sx4 = (float4*)sxp;
        #pragma unroll
        for (int r = 0; r < EPT / 4; ++r)
            sx4[tid + r * NT] = x4[tid + r * NT];
    }
    __syncthreads();

    const float w0 = sw[0], w1 = sw[1], w2 = sw[2], w3 = sw[3],
                w4 = sw[4], w5 = sw[5], w6 = sw[6];

    // ---- conv 'same' + sigmoid; keep score bits in registers; store scores early ----
    unsigned int v[EPT];
    #pragma unroll
    for (int r = 0; r < EPT; ++r) {
        int i = tid + r * NT;
        const float* p = sxp + i - 3;
        float y;
        y = p[0] * w0;
        y = fmaf(p[1], w1, y);
        y = fmaf(p[2], w2, y);
        y = fmaf(p[3], w3, y);
        y = fmaf(p[4], w4, y);
        y = fmaf(p[5], w5, y);
        y = fmaf(p[6], w6, y);
        float s = 1.0f / (1.0f + expf(-y));
        v[r] = __float_as_uint(s);         // positive floats: bit order == value order
        out[NELEM + i] = s;                // attention_score output (fire-and-forget)
    }

    // ---- block min/max to seed the search range ----
    {
        unsigned int mn = v[0], mx = v[0];
        #pragma unroll
        for (int r = 1; r < EPT; ++r) { mn = min(mn, v[r]); mx = max(mx, v[r]); }
        mn = __reduce_min_sync(0xffffffffu, mn);
        mx = __reduce_max_sync(0xffffffffu, mx);
        if (lane == 0) { wred[wid] = mn; eqm[wid] = mx; }   // eqm reused as temp
        __syncthreads();
        if (tid == 0) {
            unsigned int a = wred[0], b = eqm[0];
            #pragma unroll
            for (int q = 1; q < NWARP; ++q) { a = min(a, wred[q]); b = max(b, eqm[q]); }
            s_lo = a; s_hi = b; s_cb = 0; s_chi = NELEM;
        }
        __syncthreads();
    }

    // ---- binary search for the rank-KSEL score bits (atomic-free counting) ----
    // invariant: T* in [lo,hi]; s_cb = count(v < lo); s_chi = count(v <= hi)
    bool didA = false, inB = false;
    unsigned int lo = 0, hi = 0;
    while (true) {
        lo = s_lo; hi = s_hi;
        if (lo >= hi) break;
        unsigned int ccand = s_chi - s_cb;
        if (ccand <= POOLB) { inB = true; break; }

        if (!didA && ccand <= POOLA) {
            // one-time compaction of candidates [lo,hi] into poolA
            #pragma unroll
            for (int j = 0; j < POOLA / NT; ++j) poolA[tid + j * NT] = SENT;
            if (tid == 0) { s_pc = 0; s_baseA = s_cb; }
            __syncthreads();
            unsigned int span = hi - lo;
            unsigned int nc = 0;
            #pragma unroll
            for (int r = 0; r < EPT; ++r) nc += ((v[r] - lo) <= span);
            unsigned int inc = nc;
            #pragma unroll
            for (int o = 1; o < 32; o <<= 1) {
                unsigned int t = __shfl_up_sync(0xffffffffu, inc, o);
                if (lane >= o) inc += t;
            }
            unsigned int wtot = __shfl_sync(0xffffffffu, inc, 31);
            unsigned int base = 0;
            if (lane == 0) base = atomicAdd(&s_pc, wtot);
            base = __shfl_sync(0xffffffffu, base, 0);
            unsigned int off = base + inc - nc;
            #pragma unroll
            for (int r = 0; r < EPT; ++r)
                if ((v[r] - lo) <= span) poolA[off++] = v[r];
            didA = true;
            __syncthreads();
            continue;
        }

        unsigned int mid = lo + ((hi - lo) >> 1);
        unsigned int cnt = 0;
        if (didA) {
            #pragma unroll
            for (int j = 0; j < POOLA / NT; ++j) cnt += (poolA[tid + j * NT] <= mid);
        } else {
            #pragma unroll
            for (int r = 0; r < EPT; ++r) cnt += (v[r] <= mid);
        }
        cnt = __reduce_add_sync(0xffffffffu, cnt);
        if (lane == 0) wred[wid] = cnt;
        __syncthreads();
        if (tid == 0) {
            unsigned int tot = 0;
            #pragma unroll
            for (int q = 0; q < NWARP; ++q) tot += wred[q];
            unsigned int c = (didA ? s_baseA : 0u) + tot;
            if (c >= KSEL) { s_hi = mid; s_chi = c; }
            else           { s_lo = mid + 1; s_cb = c; }
        }
        __syncthreads();
    }

    if (inB) {
        // compact candidates (<=256) into poolB; single warp finishes barrier-free
        if (tid < POOLB) poolB[tid] = SENT;
        if (tid == 0) { s_pc = 0; s_baseB = s_cb; }
        __syncthreads();
        {
            unsigned int span = hi - lo;
            unsigned int nc = 0;
            #pragma unroll
            for (int r = 0; r < EPT; ++r) nc += ((v[r] - lo) <= span);
            unsigned int inc = nc;
            #pragma unroll
            for (int o = 1; o < 32; o <<= 1) {
                unsigned int t = __shfl_up_sync(0xffffffffu, inc, o);
                if (lane >= o) inc += t;
            }
            unsigned int wtot = __shfl_sync(0xffffffffu, inc, 31);
            unsigned int base = 0;
            if (lane == 0) base = atomicAdd(&s_pc, wtot);
            base = __shfl_sync(0xffffffffu, base, 0);
            unsigned int off = base + inc - nc;
            #pragma unroll
            for (int r = 0; r < EPT; ++r)
                if ((v[r] - lo) <= span) poolB[off++] = v[r];
        }
        __syncthreads();
        if (wid == 0) {
            unsigned int v2[POOLB / 32];
            #pragma unroll
            for (int j = 0; j < POOLB / 32; ++j) v2[j] = poolB[lane + 32 * j];
            unsigned int blo = s_lo, bhi = s_hi, bcb = s_cb;
            const unsigned int baseB = s_baseB;
            while (blo < bhi) {
                unsigned int mid = blo + ((bhi - blo) >> 1);
                unsigned int c2 = 0;
                #pragma unroll
                for (int j = 0; j < POOLB / 32; ++j) c2 += (v2[j] <= mid);
                c2 = __reduce_add_sync(0xffffffffu, c2);
                unsigned int c = baseB + c2;
                if (c >= KSEL) bhi = mid;
                else           { blo = mid + 1; bcb = c; }
            }
            if (lane == 0) { s_T = blo; s_cbF = bcb; }
        }
    } else {
        if (tid == 0) { s_T = s_lo; s_cbF = s_cb; }
    }
    __syncthreads();

    const unsigned int T    = s_T;
    const unsigned int remk = KSEL - s_cbF;   // # of ties at T kept (smallest indices)

    // ---- tie bitmask + chunked popc prefix (stable tie-break) ----
    if (tid < 512) eqm[tid] = 0;
    __syncthreads();
    #pragma unroll
    for (int r = 0; r < EPT; ++r) {
        int i = tid + r * NT;
        if (v[r] == T) atomicOr(&eqm[i >> 5], 1u << (i & 31));
    }
    __syncthreads();
    if (wid == 0) {
        unsigned int ps = 0;
        #pragma unroll
        for (int q = 0; q < 16; ++q) ps += __popc(eqm[lane * 16 + q]);
        unsigned int inc = ps;
        #pragma unroll
        for (int o = 1; o < 32; o <<= 1) {
            unsigned int t = __shfl_up_sync(0xffffffffu, inc, o);
            if (lane >= o) inc += t;
        }
        s_chunk[lane] = inc - ps;   // exclusive prefix per 16-word chunk
    }
    __syncthreads();

    // ---- emit new_x ----
    #pragma unroll
    for (int r = 0; r < EPT; ++r) {
        int i = tid + r * NT;
        unsigned int b = v[r];
        float s = __uint_as_float(b);
        bool keep;
        if (b < T)      keep = true;
        else if (b > T) keep = false;
        else {
            int wrd = i >> 5;
            unsigned int rank = s_chunk[wrd >> 4];
            for (int q = (wrd & ~15); q < wrd; ++q) rank += __popc(eqm[q]);
            rank += __popc(eqm[wrd] & ((1u << (i & 31)) - 1u));
            keep = (rank < remk);
        }
        out[i] = keep ? sxp[i] * (s + 1.0f) : 0.0f;
    }
}

extern "C" void kernel_launch(void* const* d_in, const int* in_sizes, int n_in,
                              void* d_out, int out_size)
{
    const float* x = (const float*)d_in[0];
    const float* w = (const float*)d_in[1];
    if (n_in >= 2 && in_sizes[0] == 7) {   // defensive input-order check
        const float* t = x; x = w; w = t;
    }
    float* out = (float*)d_out;

    size_t smem = (size_t)(NELEM + 8) * 4          // sx
                + (size_t)POOLA * 4 + POOLB * 4    // pools
                + 512 * 4 + NWARP * 4;             // eqmask + warp sums
    cudaFuncSetAttribute(connect_attention_fused,
                         cudaFuncAttributeMaxDynamicSharedMemorySize, (int)smem);
    connect_attention_fused<<<1, NT, smem>>>(x, w, out);
}

// round 4
// speedup vs baseline: 1.8237x; 1.4258x over previous
#include <cuda_runtime.h>
#include <math.h>

#define NELEM 16384
#define KSEL  8192
#define NB    32
#define NT    512
#define NBINS 4096

// ---- persistent scratch (no allocation allowed) ----
__device__ unsigned int g_hist[NBINS];
__device__ unsigned int g_bmin[NB];
__device__ unsigned int g_bmax[NB];
__device__ unsigned int g_candV[NELEM];
__device__ int          g_candI[NELEM];
__device__ unsigned int g_ccount;
__device__ unsigned int g_bar_count;   // zero-init at load; self-resets
__device__ unsigned int g_bar_gen;     // monotonically increasing generation

__device__ __forceinline__ void grid_bar()
{
    __syncthreads();
    if (threadIdx.x == 0) {
        __threadfence();
        unsigned int my  = atomicAdd(&g_bar_gen, 0u);     // coherent read of gen
        unsigned int old = atomicAdd(&g_bar_count, 1u);
        if (old == NB - 1) {
            atomicExch(&g_bar_count, 0u);
            __threadfence();
            atomicAdd(&g_bar_gen, 1u);                    // release
        } else {
            while (atomicAdd(&g_bar_gen, 0u) == my) { }   // acquire poll
        }
    }
    __syncthreads();
}

__global__ __launch_bounds__(NT, 1)
void connect_attention_msm(const float* __restrict__ x,
                           const float* __restrict__ w7,
                           float* __restrict__ out)
{
    __shared__ unsigned int sm_a[16], sm_b[16];
    __shared__ unsigned int s_lo, s_hi;
    __shared__ unsigned int s_bstar, s_cbase;

    const int tid  = threadIdx.x;
    const int lane = tid & 31;
    const int wid  = tid >> 5;
    const int gid  = blockIdx.x * NT + tid;

    // ================= Phase A: conv + sigmoid (1 elem/thread) =================
    const float w0 = __ldg(w7 + 0), w1 = __ldg(w7 + 1), w2 = __ldg(w7 + 2),
                w3 = __ldg(w7 + 3), w4 = __ldg(w7 + 4), w5 = __ldg(w7 + 5),
                w6 = __ldg(w7 + 6);

    const float x_i = __ldg(x + gid);
    float y = x_i * w3;
    if (gid >= 3)         y = fmaf(__ldg(x + gid - 3), w0, y);
    if (gid >= 2)         y = fmaf(__ldg(x + gid - 2), w1, y);
    if (gid >= 1)         y = fmaf(__ldg(x + gid - 1), w2, y);
    if (gid + 1 < NELEM)  y = fmaf(__ldg(x + gid + 1), w4, y);
    if (gid + 2 < NELEM)  y = fmaf(__ldg(x + gid + 2), w5, y);
    if (gid + 3 < NELEM)  y = fmaf(__ldg(x + gid + 3), w6, y);

    const float s = 1.0f / (1.0f + expf(-y));
    const unsigned int v = __float_as_uint(s);   // positive: bit order == value order
    out[NELEM + gid] = s;                        // attention_score output

    // zero shared scratch for this run (pre-bar1)
    if (tid < NBINS / NB) g_hist[blockIdx.x * (NBINS / NB) + tid] = 0;
    if (gid == 0) g_ccount = 0;

    // block min/max -> per-block slots (no atomics, overwritten every run)
    {
        unsigned int mn = __reduce_min_sync(0xffffffffu, v);
        unsigned int mx = __reduce_max_sync(0xffffffffu, v);
        if (lane == 0) { sm_a[wid] = mn; sm_b[wid] = mx; }
        __syncthreads();
        if (wid == 0) {
            unsigned int a = sm_a[lane & 15], b = sm_b[lane & 15];
            a = __reduce_min_sync(0xffffffffu, a);
            b = __reduce_max_sync(0xffffffffu, b);
            if (lane == 0) { g_bmin[blockIdx.x] = a; g_bmax[blockIdx.x] = b; }
        }
    }

    grid_bar();   // ---- bar1: min/max + zeroed hist visible everywhere ----

    // ================= Phase B: global linear histogram =================
    if (wid == 0) {
        unsigned int a = __ldcg(&g_bmin[lane]);     // NB == 32
        unsigned int b = __ldcg(&g_bmax[lane]);
        a = __reduce_min_sync(0xffffffffu, a);
        b = __reduce_max_sync(0xffffffffu, b);
        if (lane == 0) { s_lo = a; s_hi = b; }
    }
    __syncthreads();
    const unsigned int lo   = s_lo;
    const unsigned int span = s_hi - lo;
    const int bitlen = 32 - __clz(span);            // __clz(0)==32 -> bitlen 0
    const int shift  = bitlen > 12 ? bitlen - 12 : 0;
    const int bin    = (int)((v - lo) >> shift);    // < NBINS

    atomicAdd(&g_hist[bin], 1u);

    grid_bar();   // ---- bar2: histogram complete ----

    // ================= Phase C: redundant scan -> boundary bin =================
    {
        unsigned int h[8];
        unsigned int local = 0;
        #pragma unroll
        for (int q = 0; q < 8; ++q) { h[q] = __ldcg(&g_hist[tid * 8 + q]); local += h[q]; }

        unsigned int inc = local;
        #pragma unroll
        for (int o = 1; o < 32; o <<= 1) {
            unsigned int t = __shfl_up_sync(0xffffffffu, inc, o);
            if (lane >= o) inc += t;
        }
        if (lane == 31) sm_a[wid] = inc;
        __syncthreads();
        if (wid == 0) {
            unsigned int wsum = (lane < 16) ? sm_a[lane] : 0u;
            unsigned int winc = wsum;
            #pragma unroll
            for (int o = 1; o < 16; o <<= 1) {
                unsigned int t = __shfl_up_sync(0xffffffffu, winc, o);
                if (lane >= o) winc += t;
            }
            if (lane < 16) sm_b[lane] = winc - wsum;   // exclusive warp base
        }
        __syncthreads();
        unsigned int base = sm_b[wid] + inc - local;   // exclusive prefix of this thread

        if (base < KSEL && base + local >= KSEL) {     // exactly one thread
            unsigned int c = base;
            #pragma unroll
            for (int q = 0; q < 8; ++q) {
                if (c + h[q] >= KSEL) { s_bstar = (unsigned)(tid * 8 + q); s_cbase = c; break; }
                c += h[q];
            }
        }
    }
    __syncthreads();
    const int          bstar = (int)s_bstar;
    const unsigned int jkeep = KSEL - s_cbase;   // # kept from boundary bin

    // register candidates (expected handful)
    if (bin == bstar) {
        unsigned int t = atomicAdd(&g_ccount, 1u);
        g_candV[t] = v;
        g_candI[t] = gid;
    }

    grid_bar();   // ---- bar3: candidate list complete ----

    // ================= Phase D/E: stable rank among candidates + emit =================
    bool keep;
    if (bin < bstar)      keep = true;
    else if (bin > bstar) keep = false;
    else {
        const unsigned int nc = __ldcg(&g_ccount);
        unsigned int rank = 0;
        for (unsigned int t = 0; t < nc; ++t) {
            unsigned int vt = __ldcg(&g_candV[t]);
            int          it = __ldcg(&g_candI[t]);
            rank += (vt < v) || (vt == v && it < gid);
        }
        keep = (rank < jkeep);
    }
    out[gid] = keep ? x_i * (s + 1.0f) : 0.0f;
}

extern "C" void kernel_launch(void* const* d_in, const int* in_sizes, int n_in,
                              void* d_out, int out_size)
{
    const float* x = (const float*)d_in[0];
    const float* w = (const float*)d_in[1];
    if (n_in >= 2 && in_sizes[0] == 7) {   // defensive input-order check
        const float* t = x; x = w; w = t;
    }
    float* out = (float*)d_out;

    connect_attention_msm<<<NB, NT>>>(x, w, out);
}